// round 10
// baseline (speedup 1.0000x reference)
#include <cuda_runtime.h>

#define NND 100000
#define NE  1250000
#define HID 64
#define CSR_BLOCKS 98
#define CSR_THREADS 1024

#define APSTRIDE1 66   // sAp pair stride in ulls (K=64 + pad)

// ---------------- scratch (device globals; no allocation allowed) ----------
__device__ float g_h0[NND * HID];
__device__ float g_h1[NND * HID];
__device__ float g_agg[NND * HID];
__device__ int   g_cnt[NND];
__device__ int   g_rowstart[NND];
__device__ int   g_cursor[NND];
__device__ int   g_adj[NE];
__device__ int   g_blocksum[CSR_BLOCKS];
__device__ int   g_bar_count;
__device__ int   g_bar_sense;

typedef unsigned long long ull;

__device__ __forceinline__ ull pack2(float v) {
    ull r; asm("mov.b64 %0, {%1, %1};" : "=l"(r) : "f"(v)); return r;
}
__device__ __forceinline__ ull packf2(float lo, float hi) {
    ull r; asm("mov.b64 %0, {%1, %2};" : "=l"(r) : "f"(lo), "f"(hi)); return r;
}
__device__ __forceinline__ void fma2(ull& d, ull a, ull b) {
    asm("fma.rn.f32x2 %0, %1, %2, %0;" : "+l"(d) : "l"(a), "l"(b));
}
__device__ __forceinline__ float2 unpk(ull v) {
    float2 r; asm("mov.b64 {%0, %1}, %2;" : "=f"(r.x), "=f"(r.y) : "l"(v)); return r;
}
__device__ __forceinline__ float prelu(float v, float a) { return v >= 0.f ? v : a * v; }

// ---------------- launch 1: gather h0 + zero cnt + reset barrier ------------
__global__ void prep_kernel(const int* __restrict__ x,
                            const float* __restrict__ emb,
                            float* __restrict__ h0) {
    int t = blockIdx.x * blockDim.x + threadIdx.x;
    if (t < NND) g_cnt[t] = 0;
    if (t == 0) { g_bar_count = 0; g_bar_sense = 0; }
    int i = t >> 4;
    int p = (t & 15) << 2;
    int xi = __ldg(&x[i]);
    *(float4*)&h0[i * HID + p] = *(const float4*)&emb[xi * HID + p];
}

// ---------------- software grid barrier -------------------------------------
__device__ __forceinline__ void grid_barrier(int phase) {
    __threadfence();
    __syncthreads();
    if (threadIdx.x == 0) {
        int v = atomicAdd(&g_bar_count, 1);
        if (v == CSR_BLOCKS - 1) {
            atomicExch(&g_bar_count, 0);
            __threadfence();
            atomicExch(&g_bar_sense, phase);
        } else {
            while (true) {
                int s;
                asm volatile("ld.global.cg.s32 %0, [%1];" : "=r"(s) : "l"(&g_bar_sense));
                if (s >= phase) break;
                __nanosleep(64);
            }
        }
    }
    __syncthreads();
}

// ---------------- launch 2: persistent CSR build (count+scan+fill) ----------
__global__ __launch_bounds__(CSR_THREADS) void csr_kernel(const int* __restrict__ ei) {
    const int tid = threadIdx.x, bid = blockIdx.x;
    const int gid = bid * CSR_THREADS + tid;
    const int gstride = CSR_BLOCKS * CSR_THREADS;

    // phase 1: degree count (g_cnt zeroed by prep_kernel)
    for (int e = gid; e < NE; e += gstride)
        atomicAdd(&g_cnt[__ldg(&ei[NE + e])], 1);
    grid_barrier(1);

    // phase 2: intra-block exclusive scan
    __shared__ int swarp[32];
    __shared__ int soff[CSR_BLOCKS];
    int v = 0;
    if (gid < NND)
        asm volatile("ld.global.cg.s32 %0, [%1];" : "=r"(v) : "l"(&g_cnt[gid]));
    const int lane = tid & 31, wid = tid >> 5;
    int x = v;
    #pragma unroll
    for (int d = 1; d < 32; d <<= 1) { int t = __shfl_up_sync(~0u, x, d); if (lane >= d) x += t; }
    if (lane == 31) swarp[wid] = x;
    __syncthreads();
    if (wid == 0) {
        int y = swarp[lane];
        int z = y;
        #pragma unroll
        for (int d = 1; d < 32; d <<= 1) { int t = __shfl_up_sync(~0u, z, d); if (lane >= d) z += t; }
        swarp[lane] = z - y;
    }
    __syncthreads();
    const int excl = x - v + swarp[wid];
    if (tid == CSR_THREADS - 1) g_blocksum[bid] = excl + v;
    grid_barrier(2);

    // phase 3: cross-block offsets -> rowstart + cursor
    if (tid < CSR_BLOCKS) {
        int b;
        asm volatile("ld.global.cg.s32 %0, [%1];" : "=r"(b) : "l"(&g_blocksum[tid]));
        soff[tid] = b;
    }
    __syncthreads();
    if (tid == 0) {
        int run = 0;
        for (int i = 0; i < CSR_BLOCKS; i++) { int t = soff[i]; soff[i] = run; run += t; }
    }
    __syncthreads();
    if (gid < NND) {
        int st = excl + soff[bid];
        g_rowstart[gid] = st;
        g_cursor[gid] = st;
    }
    grid_barrier(3);

    // phase 4: bucket fill
    for (int e = gid; e < NE; e += gstride) {
        int src = __ldg(&ei[e]);
        int dst = __ldg(&ei[NE + e]);
        int pp = atomicAdd(&g_cursor[dst], 1);
        g_adj[pp] = src;
    }
}

// ---------------- mean aggregation (prefetched adj batches) -----------------
__global__ __launch_bounds__(256) void agg_kernel(const float* __restrict__ h,
                                                  float* __restrict__ aggout) {
    const int tid = threadIdx.x;
    const int gid = blockIdx.x * 256 + tid;
    const int node = gid >> 4;
    if (node >= NND) return;
    const int lane16 = tid & 15;
    const int p4 = lane16 << 2;
    const unsigned smask = 0xFFFFu << (tid & 16);

    const int st = __ldg(&g_rowstart[node]);
    const int n  = __ldg(&g_cnt[node]);
    float4 acc = make_float4(0.f, 0.f, 0.f, 0.f);

    // prefetch first adj batch
    int idx = 0;
    if (n > 0 && lane16 < n) idx = __ldg(&g_adj[st + lane16]);

    for (int j = 0; j < n; j += 16) {
        const int m = min(16, n - j);
        // prefetch next batch while current rows are gathered
        int idx_next = 0;
        const int jn = j + 16;
        if (jn < n && lane16 < n - jn) idx_next = __ldg(&g_adj[st + jn + lane16]);

        int jj = 0;
        for (; jj + 4 <= m; jj += 4) {
            int s0 = __shfl_sync(smask, idx, jj + 0, 16);
            int s1 = __shfl_sync(smask, idx, jj + 1, 16);
            int s2 = __shfl_sync(smask, idx, jj + 2, 16);
            int s3 = __shfl_sync(smask, idx, jj + 3, 16);
            float4 v0 = *(const float4*)&h[s0 * HID + p4];
            float4 v1 = *(const float4*)&h[s1 * HID + p4];
            float4 v2 = *(const float4*)&h[s2 * HID + p4];
            float4 v3 = *(const float4*)&h[s3 * HID + p4];
            acc.x += (v0.x + v1.x) + (v2.x + v3.x);
            acc.y += (v0.y + v1.y) + (v2.y + v3.y);
            acc.z += (v0.z + v1.z) + (v2.z + v3.z);
            acc.w += (v0.w + v1.w) + (v2.w + v3.w);
        }
        for (; jj < m; jj++) {
            int s0 = __shfl_sync(smask, idx, jj, 16);
            float4 v0 = *(const float4*)&h[s0 * HID + p4];
            acc.x += v0.x; acc.y += v0.y; acc.z += v0.z; acc.w += v0.w;
        }
        idx = idx_next;
    }
    const float iv = 1.0f / (float)max(n, 1);
    *(float4*)&aggout[node * HID + p4] =
        make_float4(acc.x * iv, acc.y * iv, acc.z * iv, acc.w * iv);
}

// ---------------- dual GEMM, K split into 2 phases (mean, h) ----------------
// chunk = 128 nodes = 64 pairs, ~67KB smem -> 3 CTAs/SM.
// warp = 2 halves x 16 lanes; half = 4 pairs x 64 cols (4 cols/lane).
__global__ __launch_bounds__(256, 3) void gemm_dual_kernel(
    const float* __restrict__ h, const float* __restrict__ agg,
    const float* __restrict__ Wl, const float* __restrict__ bl,
    const float* __restrict__ Wr, const float* __restrict__ alpha_p,
    float* __restrict__ out)
{
    extern __shared__ float sm[];
    float* sW = sm;                                  // 128*64 floats (Wl ; Wr)
    float* sb = sW + 128 * 64;                       // 64
    ull*   sAp = (ull*)(sb + 64);                    // 64 pairs * APSTRIDE1 ulls

    const int tid = threadIdx.x;
    #pragma unroll
    for (int t = tid; t < 128 * 16; t += 256) {
        int k = t >> 4, q = (t & 15) << 2;
        float4 w = (k < 64) ? *(const float4*)&Wl[k * HID + q]
                            : *(const float4*)&Wr[(k - 64) * HID + q];
        *(float4*)&sW[k * 64 + q] = w;
    }
    if (tid < HID) sb[tid] = bl[tid];
    const float alpha = __ldg(alpha_p);
    __syncthreads();    // sb/sW visible to ALL threads before acc init

    const int lane  = tid & 31;
    const int wid   = tid >> 5;
    const int half  = lane >> 4;
    const int lane16 = lane & 15;
    const int pbase = (wid << 3) + (half << 2);      // 4 pairs per half
    const int c4 = lane16 << 2;                      // 4 cols per lane
    const int nchunks = (NND + 127) / 128;           // 782

    for (int chunk = blockIdx.x; chunk < nchunks; chunk += gridDim.x) {
        const int base = chunk * 128;

        ull acc[4][4];
        {
            float4 bv = *(const float4*)&sb[c4];
            #pragma unroll
            for (int i = 0; i < 4; i++) {
                acc[i][0] = pack2(bv.x); acc[i][1] = pack2(bv.y);
                acc[i][2] = pack2(bv.z); acc[i][3] = pack2(bv.w);
            }
        }

        #pragma unroll
        for (int phase = 0; phase < 2; phase++) {
            const float* src = phase ? h : agg;
            const int wofs = phase << 6;             // W rows 0..63 / 64..127
            __syncthreads();                          // buffer safe to overwrite
            #pragma unroll
            for (int it = 0; it < 4; it++) {
                int idx = it * 256 + tid;
                int p  = idx >> 4;
                int kq = (idx & 15) << 2;
                int n0 = base + (p << 1), n1 = n0 + 1;
                float4 a0 = make_float4(0.f, 0.f, 0.f, 0.f);
                float4 a1 = make_float4(0.f, 0.f, 0.f, 0.f);
                if (n0 < NND) a0 = *(const float4*)&src[n0 * HID + kq];
                if (n1 < NND) a1 = *(const float4*)&src[n1 * HID + kq];
                ull* dst = &sAp[p * APSTRIDE1 + kq];
                dst[0] = packf2(a0.x, a1.x);
                dst[1] = packf2(a0.y, a1.y);
                dst[2] = packf2(a0.z, a1.z);
                dst[3] = packf2(a0.w, a1.w);
            }
            __syncthreads();

            #pragma unroll 4
            for (int kb = 0; kb < 64; kb += 2) {
                float4 w0 = *(const float4*)&sW[(wofs + kb) * 64 + c4];
                float4 w1 = *(const float4*)&sW[(wofs + kb + 1) * 64 + c4];
                ull wp0[4] = { pack2(w0.x), pack2(w0.y), pack2(w0.z), pack2(w0.w) };
                ull wp1[4] = { pack2(w1.x), pack2(w1.y), pack2(w1.z), pack2(w1.w) };
                ulonglong2 A[4];
                #pragma unroll
                for (int i = 0; i < 4; i++)
                    A[i] = *(const ulonglong2*)&sAp[(pbase + i) * APSTRIDE1 + kb];
                #pragma unroll
                for (int i = 0; i < 4; i++) {
                    fma2(acc[i][0], A[i].x, wp0[0]); fma2(acc[i][1], A[i].x, wp0[1]);
                    fma2(acc[i][2], A[i].x, wp0[2]); fma2(acc[i][3], A[i].x, wp0[3]);
                    fma2(acc[i][0], A[i].y, wp1[0]); fma2(acc[i][1], A[i].y, wp1[1]);
                    fma2(acc[i][2], A[i].y, wp1[2]); fma2(acc[i][3], A[i].y, wp1[3]);
                }
            }
        }

        #pragma unroll
        for (int i = 0; i < 4; i++) {
            int n0 = base + ((pbase + i) << 1), n1 = n0 + 1;
            float2 v0 = unpk(acc[i][0]), v1 = unpk(acc[i][1]);
            float2 v2 = unpk(acc[i][2]), v3 = unpk(acc[i][3]);
            if (n0 < NND)
                *(float4*)&out[n0 * HID + c4] =
                    make_float4(prelu(v0.x, alpha), prelu(v1.x, alpha),
                                prelu(v2.x, alpha), prelu(v3.x, alpha));
            if (n1 < NND)
                *(float4*)&out[n1 * HID + c4] =
                    make_float4(prelu(v0.y, alpha), prelu(v1.y, alpha),
                                prelu(v2.y, alpha), prelu(v3.y, alpha));
        }
    }
}

// ---------------- single GEMM (K=64), half-warp split, 4 CTAs/SM ------------
__global__ __launch_bounds__(256, 4) void gemm_single_kernel(
    const float* __restrict__ h,
    const float* __restrict__ W, const float* __restrict__ bb,
    float* __restrict__ out)
{
    extern __shared__ float sm[];
    float* sW = sm;                                  // 64*64
    float* sb = sW + 64 * 64;                        // 64
    ull*   sAp = (ull*)(sb + 64);                    // 64 pairs * APSTRIDE1

    const int tid = threadIdx.x;
    #pragma unroll
    for (int t = tid; t < 64 * 16; t += 256) {
        int k = t >> 4, q = (t & 15) << 2;
        *(float4*)&sW[k * 64 + q] = *(const float4*)&W[k * HID + q];
    }
    if (tid < HID) sb[tid] = bb[tid];
    __syncthreads();   // sb/sW visible before any use

    const int lane  = tid & 31;
    const int wid   = tid >> 5;
    const int half  = lane >> 4;
    const int lane16 = lane & 15;
    const int pbase = (wid << 3) + (half << 2);
    const int c4 = lane16 << 2;
    const int nchunks = (NND + 127) / 128;

    for (int chunk = blockIdx.x; chunk < nchunks; chunk += gridDim.x) {
        const int base = chunk * 128;
        __syncthreads();
        #pragma unroll
        for (int it = 0; it < 4; it++) {
            int idx = it * 256 + tid;
            int p  = idx >> 4;
            int kq = (idx & 15) << 2;
            int n0 = base + (p << 1), n1 = n0 + 1;
            float4 a0 = make_float4(0.f, 0.f, 0.f, 0.f);
            float4 a1 = make_float4(0.f, 0.f, 0.f, 0.f);
            if (n0 < NND) a0 = *(const float4*)&h[n0 * HID + kq];
            if (n1 < NND) a1 = *(const float4*)&h[n1 * HID + kq];
            ull* dst = &sAp[p * APSTRIDE1 + kq];
            dst[0] = packf2(a0.x, a1.x);
            dst[1] = packf2(a0.y, a1.y);
            dst[2] = packf2(a0.z, a1.z);
            dst[3] = packf2(a0.w, a1.w);
        }
        __syncthreads();

        ull acc[4][4];
        {
            float4 bv = *(const float4*)&sb[c4];
            #pragma unroll
            for (int i = 0; i < 4; i++) {
                acc[i][0] = pack2(bv.x); acc[i][1] = pack2(bv.y);
                acc[i][2] = pack2(bv.z); acc[i][3] = pack2(bv.w);
            }
        }

        #pragma unroll 4
        for (int kb = 0; kb < 64; kb += 2) {
            float4 w0 = *(const float4*)&sW[kb * 64 + c4];
            float4 w1 = *(const float4*)&sW[(kb + 1) * 64 + c4];
            ull wp0[4] = { pack2(w0.x), pack2(w0.y), pack2(w0.z), pack2(w0.w) };
            ull wp1[4] = { pack2(w1.x), pack2(w1.y), pack2(w1.z), pack2(w1.w) };
            ulonglong2 A[4];
            #pragma unroll
            for (int i = 0; i < 4; i++)
                A[i] = *(const ulonglong2*)&sAp[(pbase + i) * APSTRIDE1 + kb];
            #pragma unroll
            for (int i = 0; i < 4; i++) {
                fma2(acc[i][0], A[i].x, wp0[0]); fma2(acc[i][1], A[i].x, wp0[1]);
                fma2(acc[i][2], A[i].x, wp0[2]); fma2(acc[i][3], A[i].x, wp0[3]);
                fma2(acc[i][0], A[i].y, wp1[0]); fma2(acc[i][1], A[i].y, wp1[1]);
                fma2(acc[i][2], A[i].y, wp1[2]); fma2(acc[i][3], A[i].y, wp1[3]);
            }
        }

        #pragma unroll
        for (int i = 0; i < 4; i++) {
            int n0 = base + ((pbase + i) << 1), n1 = n0 + 1;
            float2 v0 = unpk(acc[i][0]), v1 = unpk(acc[i][1]);
            float2 v2 = unpk(acc[i][2]), v3 = unpk(acc[i][3]);
            if (n0 < NND)
                *(float4*)&out[n0 * HID + c4] = make_float4(v0.x, v1.x, v2.x, v3.x);
            if (n1 < NND)
                *(float4*)&out[n1 * HID + c4] = make_float4(v0.y, v1.y, v2.y, v3.y);
        }
    }
}

// ---------------- launch -----------------------------------------------------
extern "C" void kernel_launch(void* const* d_in, const int* in_sizes, int n_in,
                              void* d_out, int out_size) {
    const int*   x    = (const int*)d_in[0];
    const int*   ei   = (const int*)d_in[1];
    // d_in[2] = edge_weight : unused by the reference
    const float* emb  = (const float*)d_in[3];
    const float* Wl1  = (const float*)d_in[4];
    const float* bl1  = (const float*)d_in[5];
    const float* Wr1  = (const float*)d_in[6];
    const float* a1   = (const float*)d_in[7];
    const float* Wl2  = (const float*)d_in[8];
    const float* bl2  = (const float*)d_in[9];
    const float* Wr2  = (const float*)d_in[10];
    const float* a2   = (const float*)d_in[11];
    const float* Wout = (const float*)d_in[12];
    const float* bout = (const float*)d_in[13];
    float* out = (float*)d_out;

    float *h0, *h1, *agg;
    cudaGetSymbolAddress((void**)&h0,  g_h0);
    cudaGetSymbolAddress((void**)&h1,  g_h1);
    cudaGetSymbolAddress((void**)&agg, g_agg);

    const size_t smem_dual   = (128 * 64 + 64) * sizeof(float) + 64 * APSTRIDE1 * sizeof(ull); // ~67KB
    const size_t smem_single = (64 * 64 + 64)  * sizeof(float) + 64 * APSTRIDE1 * sizeof(ull); // ~50KB
    cudaFuncSetAttribute(gemm_dual_kernel,
                         cudaFuncAttributeMaxDynamicSharedMemorySize, (int)smem_dual);
    cudaFuncSetAttribute(gemm_single_kernel,
                         cudaFuncAttributeMaxDynamicSharedMemorySize, (int)smem_single);

    const int g_agg_grid = (NND * 16) / 256;   // 6250

    prep_kernel<<<g_agg_grid, 256>>>(x, emb, h0);
    csr_kernel<<<CSR_BLOCKS, CSR_THREADS>>>(ei);

    // layer 1
    agg_kernel<<<g_agg_grid, 256>>>(h0, agg);
    gemm_dual_kernel<<<391, 256, smem_dual>>>(h0, agg, Wl1, bl1, Wr1, a1, h1);

    // layer 2
    agg_kernel<<<g_agg_grid, 256>>>(h1, agg);
    gemm_dual_kernel<<<391, 256, smem_dual>>>(h1, agg, Wl2, bl2, Wr2, a2, h0);

    // output projection
    gemm_single_kernel<<<391, 256, smem_single>>>(h0, Wout, bout, out);
}